// round 14
// baseline (speedup 1.0000x reference)
#include <cuda_runtime.h>
#include <math.h>

#define ROWS 64
#define NTHR 1024
#define TS 68   // transposed stride (floats): affine addressing, 16B-aligned blocks

typedef unsigned long long ull;
union F4U { float4 f; ull u[2]; };

__device__ __forceinline__ int TX(int k, int r) { return k * TS + r; }

__device__ __forceinline__ float siluf(float x) {
    return x / (1.0f + __expf(-x));
}

__device__ __forceinline__ ull pk2(float lo, float hi) {
    ull r;
    asm("mov.b64 %0, {%1, %2};" : "=l"(r) : "f"(lo), "f"(hi));
    return r;
}
__device__ __forceinline__ void upk2(ull v, float& lo, float& hi) {
    asm("mov.b64 {%0, %1}, %2;" : "=f"(lo), "=f"(hi) : "l"(v));
}
__device__ __forceinline__ void fma2(ull& d, ull a, ull b) {
    asm("fma.rn.f32x2 %0, %1, %2, %0;" : "+l"(d) : "l"(a), "l"(b));
}

// Exact Plackett-Luce log-prob of an unordered 5-set via subset DP.
__device__ __forceinline__ float pl_lp(const float e[5], float S, float m, float Z) {
    float g[32];
    float sE[32];
    g[0] = 1.0f;
    sE[0] = 0.0f;
#pragma unroll
    for (int mask = 1; mask < 32; ++mask) {
        float se = 0.0f;
        float acc = 0.0f;
#pragma unroll
        for (int i = 0; i < 5; ++i) {
            if (mask & (1 << i)) {
                int sub = mask ^ (1 << i);
                se += e[i];
                acc += g[sub] * __fdividef(1.0f, Z - sE[sub]);
            }
        }
        sE[mask] = se;
        g[mask] = acc;
    }
    return S - 5.0f * m + logf(g[31]);
}

// Warp-collective top-5 over 64 values (2 per lane). Tie-break: smaller index.
__device__ __forceinline__ void warp_top5(float v0, float v1, int lane, int sel[5]) {
    int i0 = lane, i1 = lane + 32;
#pragma unroll
    for (int q = 0; q < 5; ++q) {
        float bv; int bi;
        if (v0 > v1 || (v0 == v1 && i0 < i1)) { bv = v0; bi = i0; }
        else { bv = v1; bi = i1; }
#pragma unroll
        for (int off = 16; off > 0; off >>= 1) {
            float ov = __shfl_xor_sync(0xffffffffu, bv, off);
            int   oi = __shfl_xor_sync(0xffffffffu, bi, off);
            if (ov > bv || (ov == bv && oi < bi)) { bv = ov; bi = oi; }
        }
        sel[q] = bi;
        if (bi == i0) v0 = -INFINITY;
        if (bi == i1) v1 = -INFINITY;
    }
}

__global__ void __launch_bounds__(NTHR, 1) pcf_kernel(
    const float* __restrict__ uA, const float* __restrict__ uB,
    const float* __restrict__ aLog,
    const float* __restrict__ W1, const float* __restrict__ b1,
    const float* __restrict__ W2, const float* __restrict__ b2,
    const float* __restrict__ V1, const float* __restrict__ c1,
    const float* __restrict__ V2, const float* __restrict__ c2,
    const float* __restrict__ V3, const float* __restrict__ c3,
    float* __restrict__ out, int Btot)
{
    __shared__ float sAL[64];
    __shared__ float sExpA[64];
    __shared__ float sMZ[2];
    __shared__ int   sSelA[ROWS][5];
    __shared__ int   sSelB[ROWS][5];
    __shared__ __align__(16) float bufA[256 * TS]; // H [64][128] then Z2T [256][TS]
    __shared__ __align__(16) float bufB[256 * TS]; // Z1T [256][TS]
    __shared__ __align__(16) float bufC[64 * TS];  // CtxT [64][TS] then BL [64][64]

    const int t = threadIdx.x;
    const int lane = t & 31;
    const int warp = t >> 5;
    const int b0 = blockIdx.x * ROWS;

    if (t < 64) sAL[t] = aLog[t];
    __syncthreads();

    // ---- P1: alpha softmax stats (warp 0) + alpha gumbel top-5 (2 rows/warp) ----
    if (warp == 0) {
        float l0 = sAL[lane], l1 = sAL[lane + 32];
        float m = fmaxf(l0, l1);
#pragma unroll
        for (int off = 16; off; off >>= 1) m = fmaxf(m, __shfl_xor_sync(0xffffffffu, m, off));
        float e0 = __expf(l0 - m), e1 = __expf(l1 - m);
        sExpA[lane] = e0; sExpA[lane + 32] = e1;
        float z = e0 + e1;
#pragma unroll
        for (int off = 16; off; off >>= 1) z += __shfl_xor_sync(0xffffffffu, z, off);
        if (lane == 0) { sMZ[0] = m; sMZ[1] = z; }
    }
    {
        float l0 = sAL[lane], l1 = sAL[lane + 32];
#pragma unroll
        for (int k = 0; k < 2; ++k) {
            int r = warp * 2 + k;
            int b = b0 + r;
            float u0 = uA[b * 64 + lane];
            float u1 = uA[b * 64 + lane + 32];
            float p0 = l0 - logf(-logf(fmaxf(u0, 1e-10f)));
            float p1 = l1 - logf(-logf(fmaxf(u1, 1e-10f)));
            int sel[5];
            warp_top5(p0, p1, lane, sel);
            if (lane == 0) {
                sSelA[r][0] = sel[0]; sSelA[r][1] = sel[1]; sSelA[r][2] = sel[2];
                sSelA[r][3] = sel[3]; sSelA[r][4] = sel[4];
            }
        }
    }
    __syncthreads();

    // ---- P2: h = silu(gather-sum of 5 W1 rows + b1)  [64][128] ----
    {
        float (*sH)[128] = (float(*)[128])bufA;
#pragma unroll
        for (int e = 0; e < 8; ++e) {
            int idx = t + NTHR * e;
            int r = idx >> 7, j = idx & 127;
            const int* sel = sSelA[r];
            float s = b1[j];
#pragma unroll
            for (int q = 0; q < 5; ++q) s += W1[sel[q] * 128 + j];
            sH[r][j] = siluf(s);
        }
    }
    __syncthreads();

    // ---- P3: ctx = h @ W2 + b2 -> CtxT  (4 rows x 1 col, FFMA2 over k) ----
    {
        float (*sH)[128] = (float(*)[128])bufA;
        const int j = t & 63;
        const int r0 = (t >> 6) * 4;
        const float* Wp = W2 + j;
        float bj = b2[j];
        ull acc2[4];
#pragma unroll
        for (int r = 0; r < 4; ++r) acc2[r] = pk2(bj, 0.0f);
#pragma unroll 2
        for (int kc = 0; kc < 32; ++kc) {
            float w0 = Wp[(kc * 4 + 0) * 64];
            float w1 = Wp[(kc * 4 + 1) * 64];
            float w2v = Wp[(kc * 4 + 2) * 64];
            float w3 = Wp[(kc * 4 + 3) * 64];
            ull wp01 = pk2(w0, w1), wp23 = pk2(w2v, w3);
#pragma unroll
            for (int r = 0; r < 4; ++r) {
                F4U h; h.f = *(const float4*)&sH[r0 + r][kc * 4];
                fma2(acc2[r], h.u[0], wp01);
                fma2(acc2[r], h.u[1], wp23);
            }
        }
        // contiguous in r -> one STS.128
        float res[4];
#pragma unroll
        for (int r = 0; r < 4; ++r) {
            float lo, hi; upk2(acc2[r], lo, hi);
            res[r] = lo + hi;
        }
        *(float4*)&bufC[TX(j, r0)] = make_float4(res[0], res[1], res[2], res[3]);
    }
    __syncthreads();

    // ---- P4: z1 = silu(ctx @ V1[64:,:] + c1) -> Z1T  (row-paired FFMA2) ----
    {
        const int j0 = (t & 63) * 4;
        const int r0 = (t >> 6) * 4;
        const float* Vp = V1 + 64 * 256 + j0;
        float4 bias = *(const float4*)&c1[j0];
        ull acc2[2][4];
#pragma unroll
        for (int rp = 0; rp < 2; ++rp) {
            acc2[rp][0] = pk2(bias.x, bias.x);
            acc2[rp][1] = pk2(bias.y, bias.y);
            acc2[rp][2] = pk2(bias.z, bias.z);
            acc2[rp][3] = pk2(bias.w, bias.w);
        }
#pragma unroll 2
        for (int kc = 0; kc < 16; ++kc) {
#pragma unroll
            for (int i = 0; i < 4; ++i) {
                int k = kc * 4 + i;
                F4U z; z.f = *(const float4*)&bufC[TX(k, r0)];
                float4 w = *(const float4*)&Vp[k * 256];
                ull wd0 = pk2(w.x, w.x), wd1 = pk2(w.y, w.y);
                ull wd2 = pk2(w.z, w.z), wd3 = pk2(w.w, w.w);
                fma2(acc2[0][0], z.u[0], wd0); fma2(acc2[0][1], z.u[0], wd1);
                fma2(acc2[0][2], z.u[0], wd2); fma2(acc2[0][3], z.u[0], wd3);
                fma2(acc2[1][0], z.u[1], wd0); fma2(acc2[1][1], z.u[1], wd1);
                fma2(acc2[1][2], z.u[1], wd2); fma2(acc2[1][3], z.u[1], wd3);
            }
        }
#pragma unroll
        for (int rp = 0; rp < 2; ++rp) {
#pragma unroll
            for (int c = 0; c < 4; ++c) {
                float lo, hi; upk2(acc2[rp][c], lo, hi);
                *(ull*)&bufB[TX(j0 + c, r0 + 2 * rp)] = pk2(siluf(lo), siluf(hi));
            }
        }
    }
    __syncthreads();

    // ---- P5: z2 = silu(z1 @ V2 + c2) -> Z2T  (row-paired FFMA2, dominant) ----
    {
        const int j0 = (t & 63) * 4;
        const int r0 = (t >> 6) * 4;
        const float* Vp = V2 + j0;
        float4 bias = *(const float4*)&c2[j0];
        ull acc2[2][4];
#pragma unroll
        for (int rp = 0; rp < 2; ++rp) {
            acc2[rp][0] = pk2(bias.x, bias.x);
            acc2[rp][1] = pk2(bias.y, bias.y);
            acc2[rp][2] = pk2(bias.z, bias.z);
            acc2[rp][3] = pk2(bias.w, bias.w);
        }
#pragma unroll 2
        for (int kc = 0; kc < 64; ++kc) {
#pragma unroll
            for (int i = 0; i < 4; ++i) {
                int k = kc * 4 + i;
                F4U z; z.f = *(const float4*)&bufB[TX(k, r0)];
                float4 w = *(const float4*)&Vp[k * 256];
                ull wd0 = pk2(w.x, w.x), wd1 = pk2(w.y, w.y);
                ull wd2 = pk2(w.z, w.z), wd3 = pk2(w.w, w.w);
                fma2(acc2[0][0], z.u[0], wd0); fma2(acc2[0][1], z.u[0], wd1);
                fma2(acc2[0][2], z.u[0], wd2); fma2(acc2[0][3], z.u[0], wd3);
                fma2(acc2[1][0], z.u[1], wd0); fma2(acc2[1][1], z.u[1], wd1);
                fma2(acc2[1][2], z.u[1], wd2); fma2(acc2[1][3], z.u[1], wd3);
            }
        }
#pragma unroll
        for (int rp = 0; rp < 2; ++rp) {
#pragma unroll
            for (int c = 0; c < 4; ++c) {
                float lo, hi; upk2(acc2[rp][c], lo, hi);
                *(ull*)&bufA[TX(j0 + c, r0 + 2 * rp)] = pk2(siluf(lo), siluf(hi));
            }
        }
    }
    __syncthreads();

    // ---- P6: beta_logits = z2 @ V3 + c3 -> BL [64][64]  (row-paired FFMA2) ----
    {
        float (*sBL)[64] = (float(*)[64])bufC;
        const int j = t & 63;
        const int r0 = (t >> 6) * 4;
        const float* Vp = V3 + j;
        float cj = c3[j];
        ull acc2[2];
#pragma unroll
        for (int rp = 0; rp < 2; ++rp) acc2[rp] = pk2(cj, cj);
#pragma unroll 2
        for (int kc = 0; kc < 16; ++kc) {
#pragma unroll
            for (int i = 0; i < 4; ++i) {
                int k = kc * 4 + i;
                F4U z; z.f = *(const float4*)&bufA[TX(k, r0)];
                float w = Vp[k * 64];
                ull wd = pk2(w, w);
                fma2(acc2[0], z.u[0], wd);
                fma2(acc2[1], z.u[1], wd);
            }
        }
#pragma unroll
        for (int rp = 0; rp < 2; ++rp) {
            float lo, hi; upk2(acc2[rp], lo, hi);
            sBL[r0 + 2 * rp][j]     = lo;
            sBL[r0 + 2 * rp + 1][j] = hi;
        }
    }
    __syncthreads();

    // ---- P7: beta gumbel top-5 + both PL log-probs (2 rows/warp) ----
    {
        float (*sBL)[64] = (float(*)[64])bufC;
        float mA = sMZ[0], zA = sMZ[1];
#pragma unroll
        for (int k = 0; k < 2; ++k) {
            int r = warp * 2 + k;
            int b = b0 + r;
            float l0 = sBL[r][lane], l1 = sBL[r][lane + 32];
            float u0 = uB[b * 64 + lane];
            float u1 = uB[b * 64 + lane + 32];
            float p0 = l0 - logf(-logf(fmaxf(u0, 1e-10f)));
            float p1 = l1 - logf(-logf(fmaxf(u1, 1e-10f)));
            int sel[5];
            warp_top5(p0, p1, lane, sel);
            float m = fmaxf(l0, l1);
#pragma unroll
            for (int off = 16; off; off >>= 1) m = fmaxf(m, __shfl_xor_sync(0xffffffffu, m, off));
            float z = __expf(l0 - m) + __expf(l1 - m);
#pragma unroll
            for (int off = 16; off; off >>= 1) z += __shfl_xor_sync(0xffffffffu, z, off);
            if (lane == 0) {
                sSelB[r][0] = sel[0]; sSelB[r][1] = sel[1]; sSelB[r][2] = sel[2];
                sSelB[r][3] = sel[3]; sSelB[r][4] = sel[4];
                float eb[5], Sb = 0.0f;
#pragma unroll
                for (int q = 0; q < 5; ++q) {
                    float lv = sBL[r][sel[q]];
                    Sb += lv;
                    eb[q] = __expf(lv - m);
                }
                float lpb = pl_lp(eb, Sb, m, z);
                float ea[5], Sa = 0.0f;
#pragma unroll
                for (int q = 0; q < 5; ++q) {
                    int ia = sSelA[r][q];
                    Sa += sAL[ia];
                    ea[q] = sExpA[ia];
                }
                float lpa = pl_lp(ea, Sa, mA, zA);
                out[Btot * 128 + b] = lpa + lpb;
            }
        }
    }
    __syncthreads();

    // ---- P8: write configs (0/1 masks) ----
    {
#pragma unroll
        for (int e = 0; e < 8; ++e) {
            int idx = t + NTHR * e;
            int r = idx >> 7, j = idx & 127;
            int b = b0 + r;
            float v;
            if (j < 64) {
                const int* s = sSelA[r];
                v = (j == s[0] || j == s[1] || j == s[2] || j == s[3] || j == s[4]) ? 1.0f : 0.0f;
            } else {
                int jj = j - 64;
                const int* s = sSelB[r];
                v = (jj == s[0] || jj == s[1] || jj == s[2] || jj == s[3] || jj == s[4]) ? 1.0f : 0.0f;
            }
            out[b * 128 + j] = v;
        }
    }
}

extern "C" void kernel_launch(void* const* d_in, const int* in_sizes, int n_in,
                              void* d_out, int out_size) {
    const float* uA = (const float*)d_in[0];
    const float* uB = (const float*)d_in[1];
    const float* aL = (const float*)d_in[2];
    const float* W1 = (const float*)d_in[3];
    const float* b1 = (const float*)d_in[4];
    const float* W2 = (const float*)d_in[5];
    const float* b2 = (const float*)d_in[6];
    const float* V1 = (const float*)d_in[7];
    const float* c1 = (const float*)d_in[8];
    const float* V2 = (const float*)d_in[9];
    const float* c2 = (const float*)d_in[10];
    const float* V3 = (const float*)d_in[11];
    const float* c3 = (const float*)d_in[12];
    int B = in_sizes[0] / 64;
    int grid = B / ROWS;
    pcf_kernel<<<grid, NTHR>>>(uA, uB, aL, W1, b1, W2, b2,
                               V1, c1, V2, c2, V3, c3,
                               (float*)d_out, B);
}

// round 15
// speedup vs baseline: 1.0283x; 1.0283x over previous
#include <cuda_runtime.h>
#include <math.h>

#define ROWS 64
#define NTHR 512
#define TS 68   // transposed stride (floats): affine addressing, 16B-aligned blocks

typedef unsigned long long ull;
union F4U { float4 f; ull u[2]; };
union F2U { float2 f; ull u; };

__device__ __forceinline__ int TX(int k, int r) { return k * TS + r; }

__device__ __forceinline__ float siluf(float x) {
    return x / (1.0f + __expf(-x));
}

__device__ __forceinline__ ull pk2(float lo, float hi) {
    ull r;
    asm("mov.b64 %0, {%1, %2};" : "=l"(r) : "f"(lo), "f"(hi));
    return r;
}
__device__ __forceinline__ void upk2(ull v, float& lo, float& hi) {
    asm("mov.b64 {%0, %1}, %2;" : "=f"(lo), "=f"(hi) : "l"(v));
}
__device__ __forceinline__ void fma2(ull& d, ull a, ull b) {
    asm("fma.rn.f32x2 %0, %1, %2, %0;" : "+l"(d) : "l"(a), "l"(b));
}

// Exact Plackett-Luce log-prob of an unordered 5-set via subset DP.
__device__ __forceinline__ float pl_lp(const float e[5], float S, float m, float Z) {
    float g[32];
    float sE[32];
    g[0] = 1.0f;
    sE[0] = 0.0f;
#pragma unroll
    for (int mask = 1; mask < 32; ++mask) {
        float se = 0.0f;
        float acc = 0.0f;
#pragma unroll
        for (int i = 0; i < 5; ++i) {
            if (mask & (1 << i)) {
                int sub = mask ^ (1 << i);
                se += e[i];
                acc += g[sub] * __fdividef(1.0f, Z - sE[sub]);
            }
        }
        sE[mask] = se;
        g[mask] = acc;
    }
    return S - 5.0f * m + logf(g[31]);
}

// Warp-collective top-5 over 64 values (2 per lane). Tie-break: smaller index.
__device__ __forceinline__ void warp_top5(float v0, float v1, int lane, int sel[5]) {
    int i0 = lane, i1 = lane + 32;
#pragma unroll
    for (int q = 0; q < 5; ++q) {
        float bv; int bi;
        if (v0 > v1 || (v0 == v1 && i0 < i1)) { bv = v0; bi = i0; }
        else { bv = v1; bi = i1; }
#pragma unroll
        for (int off = 16; off > 0; off >>= 1) {
            float ov = __shfl_xor_sync(0xffffffffu, bv, off);
            int   oi = __shfl_xor_sync(0xffffffffu, bi, off);
            if (ov > bv || (ov == bv && oi < bi)) { bv = ov; bi = oi; }
        }
        sel[q] = bi;
        if (bi == i0) v0 = -INFINITY;
        if (bi == i1) v1 = -INFINITY;
    }
}

__global__ void __launch_bounds__(NTHR, 1) pcf_kernel(
    const float* __restrict__ uA, const float* __restrict__ uB,
    const float* __restrict__ aLog,
    const float* __restrict__ W1, const float* __restrict__ b1,
    const float* __restrict__ W2, const float* __restrict__ b2,
    const float* __restrict__ V1, const float* __restrict__ c1,
    const float* __restrict__ V2, const float* __restrict__ c2,
    const float* __restrict__ V3, const float* __restrict__ c3,
    float* __restrict__ out, int Btot)
{
    __shared__ float sAL[64];
    __shared__ float sExpA[64];
    __shared__ float sMZ[2];
    __shared__ int   sSelA[ROWS][5];
    __shared__ int   sSelB[ROWS][5];
    __shared__ __align__(16) float bufA[256 * TS]; // H [64][128] then Z2T [256][TS]
    __shared__ __align__(16) float bufB[256 * TS]; // Z1T [256][TS]
    __shared__ __align__(16) float bufC[64 * TS];  // CtxT [64][TS] then BL [64][64]

    const int t = threadIdx.x;
    const int lane = t & 31;
    const int warp = t >> 5;
    const int b0 = blockIdx.x * ROWS;

    if (t < 64) sAL[t] = aLog[t];
    __syncthreads();

    // ---- P1: alpha softmax stats (warp 0) + alpha gumbel top-5 (4 rows/warp) ----
    if (warp == 0) {
        float l0 = sAL[lane], l1 = sAL[lane + 32];
        float m = fmaxf(l0, l1);
#pragma unroll
        for (int off = 16; off; off >>= 1) m = fmaxf(m, __shfl_xor_sync(0xffffffffu, m, off));
        float e0 = __expf(l0 - m), e1 = __expf(l1 - m);
        sExpA[lane] = e0; sExpA[lane + 32] = e1;
        float z = e0 + e1;
#pragma unroll
        for (int off = 16; off; off >>= 1) z += __shfl_xor_sync(0xffffffffu, z, off);
        if (lane == 0) { sMZ[0] = m; sMZ[1] = z; }
    }
    {
        float l0 = sAL[lane], l1 = sAL[lane + 32];
#pragma unroll
        for (int k = 0; k < 4; ++k) {
            int r = warp * 4 + k;
            int b = b0 + r;
            float u0 = uA[b * 64 + lane];
            float u1 = uA[b * 64 + lane + 32];
            float p0 = l0 - logf(-logf(fmaxf(u0, 1e-10f)));
            float p1 = l1 - logf(-logf(fmaxf(u1, 1e-10f)));
            int sel[5];
            warp_top5(p0, p1, lane, sel);
            if (lane == 0) {
                sSelA[r][0] = sel[0]; sSelA[r][1] = sel[1]; sSelA[r][2] = sel[2];
                sSelA[r][3] = sel[3]; sSelA[r][4] = sel[4];
            }
        }
    }
    __syncthreads();

    // ---- P2: h = silu(gather-sum of 5 W1 rows + b1)  [64][128] ----
    {
        float (*sH)[128] = (float(*)[128])bufA;
#pragma unroll
        for (int e = 0; e < 16; ++e) {
            int idx = t + NTHR * e;
            int r = idx >> 7, j = idx & 127;
            const int* sel = sSelA[r];
            float s = b1[j];
#pragma unroll
            for (int q = 0; q < 5; ++q) s += W1[sel[q] * 128 + j];
            sH[r][j] = siluf(s);
        }
    }
    __syncthreads();

    // ---- P3: ctx = h @ W2 + b2 -> CtxT  (8 rows x 1 col, FFMA2 over k) ----
    {
        float (*sH)[128] = (float(*)[128])bufA;
        const int j = t & 63;
        const int r0 = (t >> 6) * 8;
        const float* Wp = W2 + j;
        float bj = b2[j];
        ull acc2[8];
#pragma unroll
        for (int r = 0; r < 8; ++r) acc2[r] = pk2(bj, 0.0f);
#pragma unroll 2
        for (int kc = 0; kc < 32; ++kc) {
            float w0 = Wp[(kc * 4 + 0) * 64];
            float w1 = Wp[(kc * 4 + 1) * 64];
            float w2v = Wp[(kc * 4 + 2) * 64];
            float w3 = Wp[(kc * 4 + 3) * 64];
            ull wp01 = pk2(w0, w1), wp23 = pk2(w2v, w3);
#pragma unroll
            for (int r = 0; r < 8; ++r) {
                F4U h; h.f = *(const float4*)&sH[r0 + r][kc * 4];
                fma2(acc2[r], h.u[0], wp01);
                fma2(acc2[r], h.u[1], wp23);
            }
        }
        // contiguous in r -> two STS.128
        float res[8];
#pragma unroll
        for (int r = 0; r < 8; ++r) {
            float lo, hi; upk2(acc2[r], lo, hi);
            res[r] = lo + hi;
        }
#pragma unroll
        for (int v = 0; v < 2; ++v)
            *(float4*)&bufC[TX(j, r0 + v * 4)] = make_float4(res[v*4], res[v*4+1], res[v*4+2], res[v*4+3]);
    }
    __syncthreads();

    // ---- P4: z1 = silu(ctx @ V1[64:,:] + c1) -> Z1T  (16 rows x 2 cols) ----
    {
        const int j0 = (t & 127) * 2;
        const int r0 = (t >> 7) * 16;
        const float* Vp = V1 + 64 * 256 + j0;
        float c0 = c1[j0], c1v = c1[j0 + 1];
        ull acc2[8][2];
#pragma unroll
        for (int rp = 0; rp < 8; ++rp) {
            acc2[rp][0] = pk2(c0, c0);
            acc2[rp][1] = pk2(c1v, c1v);
        }
#pragma unroll 2
        for (int kc = 0; kc < 16; ++kc) {
#pragma unroll
            for (int i = 0; i < 4; ++i) {
                int k = kc * 4 + i;
                float2 w = *(const float2*)&Vp[k * 256];
                ull wd0 = pk2(w.x, w.x), wd1 = pk2(w.y, w.y);
                F4U z0; z0.f = *(const float4*)&bufC[TX(k, r0)];
                F4U z1; z1.f = *(const float4*)&bufC[TX(k, r0 + 4)];
                F4U z2; z2.f = *(const float4*)&bufC[TX(k, r0 + 8)];
                F4U z3; z3.f = *(const float4*)&bufC[TX(k, r0 + 12)];
                fma2(acc2[0][0], z0.u[0], wd0); fma2(acc2[0][1], z0.u[0], wd1);
                fma2(acc2[1][0], z0.u[1], wd0); fma2(acc2[1][1], z0.u[1], wd1);
                fma2(acc2[2][0], z1.u[0], wd0); fma2(acc2[2][1], z1.u[0], wd1);
                fma2(acc2[3][0], z1.u[1], wd0); fma2(acc2[3][1], z1.u[1], wd1);
                fma2(acc2[4][0], z2.u[0], wd0); fma2(acc2[4][1], z2.u[0], wd1);
                fma2(acc2[5][0], z2.u[1], wd0); fma2(acc2[5][1], z2.u[1], wd1);
                fma2(acc2[6][0], z3.u[0], wd0); fma2(acc2[6][1], z3.u[0], wd1);
                fma2(acc2[7][0], z3.u[1], wd0); fma2(acc2[7][1], z3.u[1], wd1);
            }
        }
#pragma unroll
        for (int rp = 0; rp < 8; ++rp) {
#pragma unroll
            for (int c = 0; c < 2; ++c) {
                float lo, hi; upk2(acc2[rp][c], lo, hi);
                *(ull*)&bufB[TX(j0 + c, r0 + 2 * rp)] = pk2(siluf(lo), siluf(hi));
            }
        }
    }
    __syncthreads();

    // ---- P5: z2 = silu(z1 @ V2 + c2) -> Z2T  (16 rows x 2 cols, dominant) ----
    {
        const int j0 = (t & 127) * 2;
        const int r0 = (t >> 7) * 16;
        const float* Vp = V2 + j0;
        float c0 = c2[j0], c1v = c2[j0 + 1];
        ull acc2[8][2];
#pragma unroll
        for (int rp = 0; rp < 8; ++rp) {
            acc2[rp][0] = pk2(c0, c0);
            acc2[rp][1] = pk2(c1v, c1v);
        }
#pragma unroll 2
        for (int kc = 0; kc < 64; ++kc) {
#pragma unroll
            for (int i = 0; i < 4; ++i) {
                int k = kc * 4 + i;
                float2 w = *(const float2*)&Vp[k * 256];
                ull wd0 = pk2(w.x, w.x), wd1 = pk2(w.y, w.y);
                F4U z0; z0.f = *(const float4*)&bufB[TX(k, r0)];
                F4U z1; z1.f = *(const float4*)&bufB[TX(k, r0 + 4)];
                F4U z2; z2.f = *(const float4*)&bufB[TX(k, r0 + 8)];
                F4U z3; z3.f = *(const float4*)&bufB[TX(k, r0 + 12)];
                fma2(acc2[0][0], z0.u[0], wd0); fma2(acc2[0][1], z0.u[0], wd1);
                fma2(acc2[1][0], z0.u[1], wd0); fma2(acc2[1][1], z0.u[1], wd1);
                fma2(acc2[2][0], z1.u[0], wd0); fma2(acc2[2][1], z1.u[0], wd1);
                fma2(acc2[3][0], z1.u[1], wd0); fma2(acc2[3][1], z1.u[1], wd1);
                fma2(acc2[4][0], z2.u[0], wd0); fma2(acc2[4][1], z2.u[0], wd1);
                fma2(acc2[5][0], z2.u[1], wd0); fma2(acc2[5][1], z2.u[1], wd1);
                fma2(acc2[6][0], z3.u[0], wd0); fma2(acc2[6][1], z3.u[0], wd1);
                fma2(acc2[7][0], z3.u[1], wd0); fma2(acc2[7][1], z3.u[1], wd1);
            }
        }
#pragma unroll
        for (int rp = 0; rp < 8; ++rp) {
#pragma unroll
            for (int c = 0; c < 2; ++c) {
                float lo, hi; upk2(acc2[rp][c], lo, hi);
                *(ull*)&bufA[TX(j0 + c, r0 + 2 * rp)] = pk2(siluf(lo), siluf(hi));
            }
        }
    }
    __syncthreads();

    // ---- P6: beta_logits = z2 @ V3 + c3 -> BL [64][64]  (row-paired FFMA2) ----
    {
        float (*sBL)[64] = (float(*)[64])bufC;
        const int j = t & 63;
        const int r0 = (t >> 6) * 8;
        const float* Vp = V3 + j;
        float cj = c3[j];
        ull acc2[4];
#pragma unroll
        for (int rp = 0; rp < 4; ++rp) acc2[rp] = pk2(cj, cj);
#pragma unroll 2
        for (int kc = 0; kc < 16; ++kc) {
            float w[4];
#pragma unroll
            for (int i = 0; i < 4; ++i) w[i] = Vp[(kc * 4 + i) * 64];
#pragma unroll
            for (int i = 0; i < 4; ++i) {
                int k = kc * 4 + i;
                F4U zlo; zlo.f = *(const float4*)&bufA[TX(k, r0)];
                F4U zhi; zhi.f = *(const float4*)&bufA[TX(k, r0 + 4)];
                ull wd = pk2(w[i], w[i]);
                fma2(acc2[0], zlo.u[0], wd);
                fma2(acc2[1], zlo.u[1], wd);
                fma2(acc2[2], zhi.u[0], wd);
                fma2(acc2[3], zhi.u[1], wd);
            }
        }
#pragma unroll
        for (int rp = 0; rp < 4; ++rp) {
            float lo, hi; upk2(acc2[rp], lo, hi);
            sBL[r0 + 2 * rp][j]     = lo;
            sBL[r0 + 2 * rp + 1][j] = hi;
        }
    }
    __syncthreads();

    // ---- P7: beta gumbel top-5 + both PL log-probs (4 rows/warp) ----
    {
        float (*sBL)[64] = (float(*)[64])bufC;
        float mA = sMZ[0], zA = sMZ[1];
#pragma unroll
        for (int k = 0; k < 4; ++k) {
            int r = warp * 4 + k;
            int b = b0 + r;
            float l0 = sBL[r][lane], l1 = sBL[r][lane + 32];
            float u0 = uB[b * 64 + lane];
            float u1 = uB[b * 64 + lane + 32];
            float p0 = l0 - logf(-logf(fmaxf(u0, 1e-10f)));
            float p1 = l1 - logf(-logf(fmaxf(u1, 1e-10f)));
            int sel[5];
            warp_top5(p0, p1, lane, sel);
            float m = fmaxf(l0, l1);
#pragma unroll
            for (int off = 16; off; off >>= 1) m = fmaxf(m, __shfl_xor_sync(0xffffffffu, m, off));
            float z = __expf(l0 - m) + __expf(l1 - m);
#pragma unroll
            for (int off = 16; off; off >>= 1) z += __shfl_xor_sync(0xffffffffu, z, off);
            if (lane == 0) {
                sSelB[r][0] = sel[0]; sSelB[r][1] = sel[1]; sSelB[r][2] = sel[2];
                sSelB[r][3] = sel[3]; sSelB[r][4] = sel[4];
                float eb[5], Sb = 0.0f;
#pragma unroll
                for (int q = 0; q < 5; ++q) {
                    float lv = sBL[r][sel[q]];
                    Sb += lv;
                    eb[q] = __expf(lv - m);
                }
                float lpb = pl_lp(eb, Sb, m, z);
                float ea[5], Sa = 0.0f;
#pragma unroll
                for (int q = 0; q < 5; ++q) {
                    int ia = sSelA[r][q];
                    Sa += sAL[ia];
                    ea[q] = sExpA[ia];
                }
                float lpa = pl_lp(ea, Sa, mA, zA);
                out[Btot * 128 + b] = lpa + lpb;
            }
        }
    }
    __syncthreads();

    // ---- P8: write configs (0/1 masks) ----
    {
#pragma unroll
        for (int e = 0; e < 16; ++e) {
            int idx = t + NTHR * e;
            int r = idx >> 7, j = idx & 127;
            int b = b0 + r;
            float v;
            if (j < 64) {
                const int* s = sSelA[r];
                v = (j == s[0] || j == s[1] || j == s[2] || j == s[3] || j == s[4]) ? 1.0f : 0.0f;
            } else {
                int jj = j - 64;
                const int* s = sSelB[r];
                v = (jj == s[0] || jj == s[1] || jj == s[2] || jj == s[3] || jj == s[4]) ? 1.0f : 0.0f;
            }
            out[b * 128 + j] = v;
        }
    }
}

extern "C" void kernel_launch(void* const* d_in, const int* in_sizes, int n_in,
                              void* d_out, int out_size) {
    const float* uA = (const float*)d_in[0];
    const float* uB = (const float*)d_in[1];
    const float* aL = (const float*)d_in[2];
    const float* W1 = (const float*)d_in[3];
    const float* b1 = (const float*)d_in[4];
    const float* W2 = (const float*)d_in[5];
    const float* b2 = (const float*)d_in[6];
    const float* V1 = (const float*)d_in[7];
    const float* c1 = (const float*)d_in[8];
    const float* V2 = (const float*)d_in[9];
    const float* c2 = (const float*)d_in[10];
    const float* V3 = (const float*)d_in[11];
    const float* c3 = (const float*)d_in[12];
    int B = in_sizes[0] / 64;
    int grid = B / ROWS;
    pcf_kernel<<<grid, NTHR>>>(uA, uB, aL, W1, b1, W2, b2,
                               V1, c1, V2, c2, V3, c3,
                               (float*)d_out, B);
}

// round 16
// speedup vs baseline: 1.1261x; 1.0950x over previous
#include <cuda_runtime.h>
#include <math.h>

#define ROWS 64
#define NTHR 512
#define TS 68   // transposed stride (floats): affine addressing, 16B-aligned blocks

typedef unsigned long long ull;
union F4U { float4 f; ull u[2]; };

__device__ __forceinline__ int TX(int k, int r) { return k * TS + r; }

__device__ __forceinline__ float siluf(float x) {
    return x / (1.0f + __expf(-x));
}

__device__ __forceinline__ ull pk2(float lo, float hi) {
    ull r;
    asm("mov.b64 %0, {%1, %2};" : "=l"(r) : "f"(lo), "f"(hi));
    return r;
}
__device__ __forceinline__ void upk2(ull v, float& lo, float& hi) {
    asm("mov.b64 {%0, %1}, %2;" : "=f"(lo), "=f"(hi) : "l"(v));
}
__device__ __forceinline__ void fma2(ull& d, ull a, ull b) {
    asm("fma.rn.f32x2 %0, %1, %2, %0;" : "+l"(d) : "l"(a), "l"(b));
}

// Exact Plackett-Luce log-prob of an unordered 5-set via subset DP.
__device__ __forceinline__ float pl_lp(const float e[5], float S, float m, float Z) {
    float g[32];
    float sE[32];
    g[0] = 1.0f;
    sE[0] = 0.0f;
#pragma unroll
    for (int mask = 1; mask < 32; ++mask) {
        float se = 0.0f;
        float acc = 0.0f;
#pragma unroll
        for (int i = 0; i < 5; ++i) {
            if (mask & (1 << i)) {
                int sub = mask ^ (1 << i);
                se += e[i];
                acc += g[sub] * __fdividef(1.0f, Z - sE[sub]);
            }
        }
        sE[mask] = se;
        g[mask] = acc;
    }
    return S - 5.0f * m + logf(g[31]);
}

// Warp-collective top-5 over 64 values (2 per lane). Tie-break: smaller index.
__device__ __forceinline__ void warp_top5(float v0, float v1, int lane, int sel[5]) {
    int i0 = lane, i1 = lane + 32;
#pragma unroll
    for (int q = 0; q < 5; ++q) {
        float bv; int bi;
        if (v0 > v1 || (v0 == v1 && i0 < i1)) { bv = v0; bi = i0; }
        else { bv = v1; bi = i1; }
#pragma unroll
        for (int off = 16; off > 0; off >>= 1) {
            float ov = __shfl_xor_sync(0xffffffffu, bv, off);
            int   oi = __shfl_xor_sync(0xffffffffu, bi, off);
            if (ov > bv || (ov == bv && oi < bi)) { bv = ov; bi = oi; }
        }
        sel[q] = bi;
        if (bi == i0) v0 = -INFINITY;
        if (bi == i1) v1 = -INFINITY;
    }
}

__global__ void __launch_bounds__(NTHR, 1) pcf_kernel(
    const float* __restrict__ uA, const float* __restrict__ uB,
    const float* __restrict__ aLog,
    const float* __restrict__ W1, const float* __restrict__ b1,
    const float* __restrict__ W2, const float* __restrict__ b2,
    const float* __restrict__ V1, const float* __restrict__ c1,
    const float* __restrict__ V2, const float* __restrict__ c2,
    const float* __restrict__ V3, const float* __restrict__ c3,
    float* __restrict__ out, int Btot)
{
    __shared__ float sAL[64];
    __shared__ float sExpA[64];
    __shared__ float sMZ[2];
    __shared__ int   sSelA[ROWS][5];
    __shared__ int   sSelB[ROWS][5];
    __shared__ float sMB[ROWS];
    __shared__ float sZB[ROWS];
    __shared__ __align__(16) float bufA[256 * TS]; // H [64][128] then Z2T [256][TS]
    __shared__ __align__(16) float bufB[256 * TS]; // Z1T [256][TS]
    __shared__ __align__(16) float bufC[64 * TS];  // CtxT [64][TS] then BL [64][64]

    const int t = threadIdx.x;
    const int lane = t & 31;
    const int warp = t >> 5;
    const int b0 = blockIdx.x * ROWS;

    if (t < 64) sAL[t] = aLog[t];
    __syncthreads();

    // ---- P1: alpha softmax stats (warp 0) + alpha gumbel top-5 (4 rows/warp) ----
    if (warp == 0) {
        float l0 = sAL[lane], l1 = sAL[lane + 32];
        float m = fmaxf(l0, l1);
#pragma unroll
        for (int off = 16; off; off >>= 1) m = fmaxf(m, __shfl_xor_sync(0xffffffffu, m, off));
        float e0 = __expf(l0 - m), e1 = __expf(l1 - m);
        sExpA[lane] = e0; sExpA[lane + 32] = e1;
        float z = e0 + e1;
#pragma unroll
        for (int off = 16; off; off >>= 1) z += __shfl_xor_sync(0xffffffffu, z, off);
        if (lane == 0) { sMZ[0] = m; sMZ[1] = z; }
    }
    {
        float l0 = sAL[lane], l1 = sAL[lane + 32];
#pragma unroll
        for (int k = 0; k < 4; ++k) {
            int r = warp * 4 + k;
            int b = b0 + r;
            float u0 = uA[b * 64 + lane];
            float u1 = uA[b * 64 + lane + 32];
            float p0 = l0 - logf(-logf(fmaxf(u0, 1e-10f)));
            float p1 = l1 - logf(-logf(fmaxf(u1, 1e-10f)));
            int sel[5];
            warp_top5(p0, p1, lane, sel);
            if (lane == 0) {
                sSelA[r][0] = sel[0]; sSelA[r][1] = sel[1]; sSelA[r][2] = sel[2];
                sSelA[r][3] = sel[3]; sSelA[r][4] = sel[4];
            }
        }
    }
    __syncthreads();

    // ---- P2: h = silu(gather-sum of 5 W1 rows + b1)  [64][128] ----
    {
        float (*sH)[128] = (float(*)[128])bufA;
#pragma unroll
        for (int e = 0; e < 16; ++e) {
            int idx = t + NTHR * e;
            int r = idx >> 7, j = idx & 127;
            const int* sel = sSelA[r];
            float s = b1[j];
#pragma unroll
            for (int q = 0; q < 5; ++q) s += W1[sel[q] * 128 + j];
            sH[r][j] = siluf(s);
        }
    }
    __syncthreads();

    // ---- P3: ctx = h @ W2 + b2 -> CtxT  (8 rows x 1 col, FFMA2 over k) ----
    {
        float (*sH)[128] = (float(*)[128])bufA;
        const int j = t & 63;
        const int r0 = (t >> 6) * 8;
        const float* Wp = W2 + j;
        float bj = b2[j];
        ull acc2[8];
#pragma unroll
        for (int r = 0; r < 8; ++r) acc2[r] = pk2(bj, 0.0f);
#pragma unroll 2
        for (int kc = 0; kc < 32; ++kc) {
            float w0 = Wp[(kc * 4 + 0) * 64];
            float w1 = Wp[(kc * 4 + 1) * 64];
            float w2v = Wp[(kc * 4 + 2) * 64];
            float w3 = Wp[(kc * 4 + 3) * 64];
            ull wp01 = pk2(w0, w1), wp23 = pk2(w2v, w3);
#pragma unroll
            for (int r = 0; r < 8; ++r) {
                F4U h; h.f = *(const float4*)&sH[r0 + r][kc * 4];
                fma2(acc2[r], h.u[0], wp01);
                fma2(acc2[r], h.u[1], wp23);
            }
        }
        // contiguous in r -> two STS.128
        float res[8];
#pragma unroll
        for (int r = 0; r < 8; ++r) {
            float lo, hi; upk2(acc2[r], lo, hi);
            res[r] = lo + hi;
        }
#pragma unroll
        for (int v = 0; v < 2; ++v)
            *(float4*)&bufC[TX(j, r0 + v * 4)] = make_float4(res[v*4], res[v*4+1], res[v*4+2], res[v*4+3]);
    }
    __syncthreads();

    // ---- P4: z1 = silu(ctx @ V1[64:,:] + c1) -> Z1T  (row-paired FFMA2, batched w) ----
    {
        const int j0 = (t & 63) * 4;
        const int r0 = (t >> 6) * 8;
        const float* Vp = V1 + 64 * 256 + j0;
        float4 bias = *(const float4*)&c1[j0];
        ull acc2[4][4];
#pragma unroll
        for (int rp = 0; rp < 4; ++rp) {
            acc2[rp][0] = pk2(bias.x, bias.x);
            acc2[rp][1] = pk2(bias.y, bias.y);
            acc2[rp][2] = pk2(bias.z, bias.z);
            acc2[rp][3] = pk2(bias.w, bias.w);
        }
#pragma unroll 2
        for (int kc = 0; kc < 16; ++kc) {
            float4 w[4];
#pragma unroll
            for (int i = 0; i < 4; ++i) w[i] = *(const float4*)&Vp[(kc * 4 + i) * 256];
#pragma unroll
            for (int i = 0; i < 4; ++i) {
                int k = kc * 4 + i;
                F4U zlo; zlo.f = *(const float4*)&bufC[TX(k, r0)];
                F4U zhi; zhi.f = *(const float4*)&bufC[TX(k, r0 + 4)];
                ull wd0 = pk2(w[i].x, w[i].x), wd1 = pk2(w[i].y, w[i].y);
                ull wd2 = pk2(w[i].z, w[i].z), wd3 = pk2(w[i].w, w[i].w);
                fma2(acc2[0][0], zlo.u[0], wd0); fma2(acc2[0][1], zlo.u[0], wd1);
                fma2(acc2[0][2], zlo.u[0], wd2); fma2(acc2[0][3], zlo.u[0], wd3);
                fma2(acc2[1][0], zlo.u[1], wd0); fma2(acc2[1][1], zlo.u[1], wd1);
                fma2(acc2[1][2], zlo.u[1], wd2); fma2(acc2[1][3], zlo.u[1], wd3);
                fma2(acc2[2][0], zhi.u[0], wd0); fma2(acc2[2][1], zhi.u[0], wd1);
                fma2(acc2[2][2], zhi.u[0], wd2); fma2(acc2[2][3], zhi.u[0], wd3);
                fma2(acc2[3][0], zhi.u[1], wd0); fma2(acc2[3][1], zhi.u[1], wd1);
                fma2(acc2[3][2], zhi.u[1], wd2); fma2(acc2[3][3], zhi.u[1], wd3);
            }
        }
#pragma unroll
        for (int rp = 0; rp < 4; ++rp) {
#pragma unroll
            for (int c = 0; c < 4; ++c) {
                float lo, hi; upk2(acc2[rp][c], lo, hi);
                *(ull*)&bufB[TX(j0 + c, r0 + 2 * rp)] = pk2(siluf(lo), siluf(hi));
            }
        }
    }
    __syncthreads();

    // ---- P5: z2 = silu(z1 @ V2 + c2) -> Z2T  (row-paired FFMA2, batched w, dominant) ----
    {
        const int j0 = (t & 63) * 4;
        const int r0 = (t >> 6) * 8;
        const float* Vp = V2 + j0;
        float4 bias = *(const float4*)&c2[j0];
        ull acc2[4][4];
#pragma unroll
        for (int rp = 0; rp < 4; ++rp) {
            acc2[rp][0] = pk2(bias.x, bias.x);
            acc2[rp][1] = pk2(bias.y, bias.y);
            acc2[rp][2] = pk2(bias.z, bias.z);
            acc2[rp][3] = pk2(bias.w, bias.w);
        }
#pragma unroll 2
        for (int kc = 0; kc < 64; ++kc) {
            float4 w[4];
#pragma unroll
            for (int i = 0; i < 4; ++i) w[i] = *(const float4*)&Vp[(kc * 4 + i) * 256];
#pragma unroll
            for (int i = 0; i < 4; ++i) {
                int k = kc * 4 + i;
                F4U zlo; zlo.f = *(const float4*)&bufB[TX(k, r0)];
                F4U zhi; zhi.f = *(const float4*)&bufB[TX(k, r0 + 4)];
                ull wd0 = pk2(w[i].x, w[i].x), wd1 = pk2(w[i].y, w[i].y);
                ull wd2 = pk2(w[i].z, w[i].z), wd3 = pk2(w[i].w, w[i].w);
                fma2(acc2[0][0], zlo.u[0], wd0); fma2(acc2[0][1], zlo.u[0], wd1);
                fma2(acc2[0][2], zlo.u[0], wd2); fma2(acc2[0][3], zlo.u[0], wd3);
                fma2(acc2[1][0], zlo.u[1], wd0); fma2(acc2[1][1], zlo.u[1], wd1);
                fma2(acc2[1][2], zlo.u[1], wd2); fma2(acc2[1][3], zlo.u[1], wd3);
                fma2(acc2[2][0], zhi.u[0], wd0); fma2(acc2[2][1], zhi.u[0], wd1);
                fma2(acc2[2][2], zhi.u[0], wd2); fma2(acc2[2][3], zhi.u[0], wd3);
                fma2(acc2[3][0], zhi.u[1], wd0); fma2(acc2[3][1], zhi.u[1], wd1);
                fma2(acc2[3][2], zhi.u[1], wd2); fma2(acc2[3][3], zhi.u[1], wd3);
            }
        }
#pragma unroll
        for (int rp = 0; rp < 4; ++rp) {
#pragma unroll
            for (int c = 0; c < 4; ++c) {
                float lo, hi; upk2(acc2[rp][c], lo, hi);
                *(ull*)&bufA[TX(j0 + c, r0 + 2 * rp)] = pk2(siluf(lo), siluf(hi));
            }
        }
    }
    __syncthreads();

    // ---- P6: beta_logits = z2 @ V3 + c3 -> BL [64][64]  (row-paired FFMA2, batched w) ----
    {
        float (*sBL)[64] = (float(*)[64])bufC;
        const int j = t & 63;
        const int r0 = (t >> 6) * 8;
        const float* Vp = V3 + j;
        float cj = c3[j];
        ull acc2[4];
#pragma unroll
        for (int rp = 0; rp < 4; ++rp) acc2[rp] = pk2(cj, cj);
#pragma unroll 2
        for (int kc = 0; kc < 16; ++kc) {
            float w[4];
#pragma unroll
            for (int i = 0; i < 4; ++i) w[i] = Vp[(kc * 4 + i) * 64];
#pragma unroll
            for (int i = 0; i < 4; ++i) {
                int k = kc * 4 + i;
                F4U zlo; zlo.f = *(const float4*)&bufA[TX(k, r0)];
                F4U zhi; zhi.f = *(const float4*)&bufA[TX(k, r0 + 4)];
                ull wd = pk2(w[i], w[i]);
                fma2(acc2[0], zlo.u[0], wd);
                fma2(acc2[1], zlo.u[1], wd);
                fma2(acc2[2], zhi.u[0], wd);
                fma2(acc2[3], zhi.u[1], wd);
            }
        }
#pragma unroll
        for (int rp = 0; rp < 4; ++rp) {
            float lo, hi; upk2(acc2[rp], lo, hi);
            sBL[r0 + 2 * rp][j]     = lo;
            sBL[r0 + 2 * rp + 1][j] = hi;
        }
    }
    __syncthreads();

    // ---- P7a: beta gumbel top-5 + softmax stats per row (4 rows/warp) ----
    {
        float (*sBL)[64] = (float(*)[64])bufC;
#pragma unroll
        for (int k = 0; k < 4; ++k) {
            int r = warp * 4 + k;
            int b = b0 + r;
            float l0 = sBL[r][lane], l1 = sBL[r][lane + 32];
            float u0 = uB[b * 64 + lane];
            float u1 = uB[b * 64 + lane + 32];
            float p0 = l0 - logf(-logf(fmaxf(u0, 1e-10f)));
            float p1 = l1 - logf(-logf(fmaxf(u1, 1e-10f)));
            int sel[5];
            warp_top5(p0, p1, lane, sel);
            float m = fmaxf(l0, l1);
#pragma unroll
            for (int off = 16; off; off >>= 1) m = fmaxf(m, __shfl_xor_sync(0xffffffffu, m, off));
            float z = __expf(l0 - m) + __expf(l1 - m);
#pragma unroll
            for (int off = 16; off; off >>= 1) z += __shfl_xor_sync(0xffffffffu, z, off);
            if (lane == 0) {
                sSelB[r][0] = sel[0]; sSelB[r][1] = sel[1]; sSelB[r][2] = sel[2];
                sSelB[r][3] = sel[3]; sSelB[r][4] = sel[4];
                sMB[r] = m; sZB[r] = z;
            }
        }
        __syncwarp();

        // ---- P7b: lanes 0-7 each run ONE pl_lp (4 rows x {alpha,beta}) ----
        float lp = 0.0f;
        if (lane < 8) {
            int r = warp * 4 + (lane >> 1);
            int kind = lane & 1;
            float e[5], S = 0.0f, m, Z;
            if (kind == 0) {
                m = sMZ[0]; Z = sMZ[1];
#pragma unroll
                for (int q = 0; q < 5; ++q) {
                    int ia = sSelA[r][q];
                    S += sAL[ia];
                    e[q] = sExpA[ia];
                }
            } else {
                m = sMB[r]; Z = sZB[r];
#pragma unroll
                for (int q = 0; q < 5; ++q) {
                    float lv = sBL[r][sSelB[r][q]];
                    S += lv;
                    e[q] = __expf(lv - m);
                }
            }
            lp = pl_lp(e, S, m, Z);
        }
        // combine alpha+beta per row and store
        float lpA = __shfl_sync(0xffffffffu, lp, (lane * 2) & 31);
        float lpB = __shfl_sync(0xffffffffu, lp, (lane * 2 + 1) & 31);
        if (lane < 4) out[Btot * 128 + b0 + warp * 4 + lane] = lpA + lpB;
    }
    __syncthreads();

    // ---- P8: write configs (0/1 masks) ----
    {
#pragma unroll
        for (int e = 0; e < 16; ++e) {
            int idx = t + NTHR * e;
            int r = idx >> 7, j = idx & 127;
            int b = b0 + r;
            float v;
            if (j < 64) {
                const int* s = sSelA[r];
                v = (j == s[0] || j == s[1] || j == s[2] || j == s[3] || j == s[4]) ? 1.0f : 0.0f;
            } else {
                int jj = j - 64;
                const int* s = sSelB[r];
                v = (jj == s[0] || jj == s[1] || jj == s[2] || jj == s[3] || jj == s[4]) ? 1.0f : 0.0f;
            }
            out[b * 128 + j] = v;
        }
    }
}

extern "C" void kernel_launch(void* const* d_in, const int* in_sizes, int n_in,
                              void* d_out, int out_size) {
    const float* uA = (const float*)d_in[0];
    const float* uB = (const float*)d_in[1];
    const float* aL = (const float*)d_in[2];
    const float* W1 = (const float*)d_in[3];
    const float* b1 = (const float*)d_in[4];
    const float* W2 = (const float*)d_in[5];
    const float* b2 = (const float*)d_in[6];
    const float* V1 = (const float*)d_in[7];
    const float* c1 = (const float*)d_in[8];
    const float* V2 = (const float*)d_in[9];
    const float* c2 = (const float*)d_in[10];
    const float* V3 = (const float*)d_in[11];
    const float* c3 = (const float*)d_in[12];
    int B = in_sizes[0] / 64;
    int grid = B / ROWS;
    pcf_kernel<<<grid, NTHR>>>(uA, uB, aL, W1, b1, W2, b2,
                               V1, c1, V2, c2, V3, c3,
                               (float*)d_out, B);
}